// round 5
// baseline (speedup 1.0000x reference)
#include <cuda_runtime.h>

#define BB 8
#define TT 2048
#define EE 1024
#define HH 128
#define MM (BB*TT)
#define SCALE 0.08838834764831845f   // 1/sqrt(128)

// Scratch for projected Q/K/V (tf32-rounded; Q pre-scaled)
__device__ float g_Q[MM*HH];
__device__ float g_K[MM*HH];
__device__ float g_V[MM*HH];

__device__ __forceinline__ float f2tf(float f) {
    unsigned r;
    asm("cvt.rna.tf32.f32 %0, %1;" : "=r"(r) : "f"(f));
    return __uint_as_float(r);
}

__device__ __forceinline__ void mma_tf32(float* c,
    unsigned a0, unsigned a1, unsigned a2, unsigned a3,
    unsigned b0, unsigned b1)
{
    asm volatile(
        "mma.sync.aligned.m16n8k8.row.col.f32.tf32.tf32.f32 "
        "{%0,%1,%2,%3},{%4,%5,%6,%7},{%8,%9},{%0,%1,%2,%3};"
        : "+f"(c[0]), "+f"(c[1]), "+f"(c[2]), "+f"(c[3])
        : "r"(a0), "r"(a1), "r"(a2), "r"(a3), "r"(b0), "r"(b1));
}
#define U(x) __float_as_uint(x)

// qt permutation: pairs (x, (x+20)%32) — co-resident on one SM — sum to ~31.
__constant__ int QT_MAP[32] = {
    31,27,23,19, 2, 6,10,14,30,26,22,18, 3, 7,11,15,
    29,25,21,17, 0, 4, 8,12,28,24,20,16, 1, 5, 9,13};

// ---------------------------------------------------------------------------
// Kernel 1: QKV projection (tf32 mma). Outputs tf32-rounded; Q pre-scaled.
// ---------------------------------------------------------------------------
__global__ __launch_bounds__(256) void qkv_kernel(
    const float* __restrict__ x,
    const float* __restrict__ Wq,
    const float* __restrict__ Wk,
    const float* __restrict__ Wv)
{
    __shared__ float As[128][36];
    __shared__ float Bs[32][136];

    const int mb = blockIdx.x;
    const int w3 = blockIdx.y;
    const float* Wp   = (w3 == 0) ? Wq : ((w3 == 1) ? Wk : Wv);
    float*       outp = (w3 == 0) ? g_Q : ((w3 == 1) ? g_K : g_V);
    const float  oscale = (w3 == 0) ? SCALE : 1.0f;

    const int tid  = threadIdx.x;
    const int lane = tid & 31;
    const int w    = tid >> 5;
    const int g    = lane >> 2;
    const int t4   = lane & 3;
    const int wm   = (w >> 1) * 32;
    const int wn   = (w & 1) * 64;
    const int m0   = mb * 128;

    float acc[2][8][4];
#pragma unroll
    for (int mt = 0; mt < 2; mt++)
#pragma unroll
        for (int nt = 0; nt < 8; nt++)
#pragma unroll
            for (int i = 0; i < 4; i++) acc[mt][nt][i] = 0.f;

    float4 xa[4], wa[4];
#pragma unroll
    for (int i = 0; i < 4; i++) {
        int lin = tid + i * 256;
        int r = lin >> 3, c = (lin & 7) * 4;
        xa[i] = *(const float4*)&x[(size_t)(m0 + r) * EE + c];
    }
#pragma unroll
    for (int i = 0; i < 4; i++) {
        int lin = tid + i * 256;
        int r = lin >> 5, c = (lin & 31) * 4;
        wa[i] = *(const float4*)&Wp[(size_t)r * HH + c];
    }

    for (int k0 = 0; k0 < EE; k0 += 32) {
#pragma unroll
        for (int i = 0; i < 4; i++) {
            int lin = tid + i * 256;
            int r = lin >> 3, c = (lin & 7) * 4;
            As[r][c + 0] = f2tf(xa[i].x);
            As[r][c + 1] = f2tf(xa[i].y);
            As[r][c + 2] = f2tf(xa[i].z);
            As[r][c + 3] = f2tf(xa[i].w);
        }
#pragma unroll
        for (int i = 0; i < 4; i++) {
            int lin = tid + i * 256;
            int r = lin >> 5, c = (lin & 31) * 4;
            Bs[r][c + 0] = f2tf(wa[i].x);
            Bs[r][c + 1] = f2tf(wa[i].y);
            Bs[r][c + 2] = f2tf(wa[i].z);
            Bs[r][c + 3] = f2tf(wa[i].w);
        }
        __syncthreads();

        if (k0 + 32 < EE) {
            int kn = k0 + 32;
#pragma unroll
            for (int i = 0; i < 4; i++) {
                int lin = tid + i * 256;
                int r = lin >> 3, c = (lin & 7) * 4;
                xa[i] = *(const float4*)&x[(size_t)(m0 + r) * EE + kn + c];
            }
#pragma unroll
            for (int i = 0; i < 4; i++) {
                int lin = tid + i * 256;
                int r = lin >> 5, c = (lin & 31) * 4;
                wa[i] = *(const float4*)&Wp[(size_t)(kn + r) * HH + c];
            }
        }

#pragma unroll
        for (int ks = 0; ks < 4; ks++) {
            unsigned a[2][4];
#pragma unroll
            for (int mt = 0; mt < 2; mt++) {
                a[mt][0] = U(As[wm + mt * 16 + g    ][ks * 8 + t4    ]);
                a[mt][1] = U(As[wm + mt * 16 + g + 8][ks * 8 + t4    ]);
                a[mt][2] = U(As[wm + mt * 16 + g    ][ks * 8 + t4 + 4]);
                a[mt][3] = U(As[wm + mt * 16 + g + 8][ks * 8 + t4 + 4]);
            }
#pragma unroll
            for (int nt = 0; nt < 8; nt++) {
                unsigned b0 = U(Bs[ks * 8 + t4    ][wn + nt * 8 + g]);
                unsigned b1 = U(Bs[ks * 8 + t4 + 4][wn + nt * 8 + g]);
                mma_tf32(acc[0][nt], a[0][0], a[0][1], a[0][2], a[0][3], b0, b1);
                mma_tf32(acc[1][nt], a[1][0], a[1][1], a[1][2], a[1][3], b0, b1);
            }
        }
        __syncthreads();
    }

#pragma unroll
    for (int mt = 0; mt < 2; mt++) {
#pragma unroll
        for (int nt = 0; nt < 8; nt++) {
            int row = m0 + wm + mt * 16 + g;
            int col = wn + nt * 8 + 2 * t4;
            float2 v0 = make_float2(f2tf(acc[mt][nt][0] * oscale), f2tf(acc[mt][nt][1] * oscale));
            float2 v1 = make_float2(f2tf(acc[mt][nt][2] * oscale), f2tf(acc[mt][nt][3] * oscale));
            *(float2*)&outp[(size_t)row * HH + col]       = v0;
            *(float2*)&outp[(size_t)(row + 8) * HH + col] = v1;
        }
    }
}

// ---------------------------------------------------------------------------
// Kernel 2: causal flash attention, fragment-layout smem, register softmax.
// 128 threads = 4 warps; warp wq owns q-rows [wq*16, wq*16+16) x all 64 k-cols.
// Fragment tiles: 32 lanes x 4 floats (=512B) padded to 528B (conflict spread).
// ---------------------------------------------------------------------------
#define TILE_F 132                       // floats per padded frag tile
#define ATTN_SMEM (192 * TILE_F * 4)     // Qsf 64 + Ksf 64 + Vsf 64 tiles = 101376 B

__global__ __launch_bounds__(128) void attn_kernel(float* __restrict__ out)
{
    extern __shared__ float sh[];
    float* Qsf = sh;                  // [wq*16 + ks][lane][4]   (A-frags of Q)
    float* Ksf = Qsf + 64 * TILE_F;   // [nt*8 + ksp][lane][4]   (B-frag pairs of K)
    float* Vsf = Ksf + 64 * TILE_F;   // [nt*4 + ksp][lane][4]   (B-frag pairs of V)

    const int b  = blockIdx.y;
    const int qt = QT_MAP[blockIdx.x];
    const int q0 = qt * 64;

    const int tid  = threadIdx.x;
    const int lane = tid & 31;
    const int wq   = tid >> 5;
    const int g    = lane >> 2;
    const int t4   = lane & 3;

    // ---- load Q tile into A-fragment layout ----
    const float* Qg = g_Q + ((size_t)b * TT + q0) * HH;
#pragma unroll
    for (int it = 0; it < 16; it++) {
        int idx = tid + it * 128;            // 2048 float4
        int r = idx >> 5, c4 = (idx & 31) * 4;
        float4 v = *(const float4*)&Qg[(size_t)r * HH + c4];
        int wqi = r >> 4, i = r & 15;
        float vv[4] = {v.x, v.y, v.z, v.w};
#pragma unroll
        for (int t = 0; t < 4; t++) {
            int c  = c4 + t;
            int ln = ((i & 7) << 2) | (c & 3);
            int rg = (i >> 3) | (((c >> 2) & 1) << 1);
            Qsf[(wqi * 16 + (c >> 3)) * TILE_F + ln * 4 + rg] = vv[t];
        }
    }

    float m1 = -1e30f, m2 = -1e30f, l1 = 0.f, l2 = 0.f;
    float o[16][4];
#pragma unroll
    for (int nt = 0; nt < 16; nt++)
#pragma unroll
        for (int i = 0; i < 4; i++) o[nt][i] = 0.f;

    __syncthreads();

    for (int kt = 0; kt <= qt; kt++) {
        if (kt) __syncthreads();
        const int k0 = kt * 64;
        const float* Kg = g_K + ((size_t)b * TT + k0) * HH;
        const float* Vg = g_V + ((size_t)b * TT + k0) * HH;

        // ---- load K,V tiles into B-fragment layout ----
#pragma unroll
        for (int it = 0; it < 16; it++) {
            int idx = tid + it * 128;
            int r = idx >> 5, c4 = (idx & 31) * 4;
            float4 kv = *(const float4*)&Kg[(size_t)r * HH + c4];
            float4 vv = *(const float4*)&Vg[(size_t)r * HH + c4];
            {   // K: tile (nt = r>>3, ksp = c>>4); lane 4*(r&7)+(c&3); reg (c>>2)&3
                int nt = r >> 3, gg = r & 7;
                float va[4] = {kv.x, kv.y, kv.z, kv.w};
#pragma unroll
                for (int t = 0; t < 4; t++) {
                    int c = c4 + t;
                    Ksf[(nt * 8 + (c >> 4)) * TILE_F + (((gg << 2) | (c & 3)) << 2) + ((c >> 2) & 3)] = va[t];
                }
            }
            {   // V: tile (nt = c>>3, ksp = r>>4); lane 4*(c&7)+(r&3); reg (r>>2)&3
                int ksp = r >> 4, t4v = r & 3, regv = (r >> 2) & 3;
                float va[4] = {vv.x, vv.y, vv.z, vv.w};
#pragma unroll
                for (int t = 0; t < 4; t++) {
                    int c = c4 + t;
                    Vsf[((c >> 3) * 4 + ksp) * TILE_F + ((((c & 7) << 2) | t4v) << 2) + regv] = va[t];
                }
            }
        }
        __syncthreads();

        // ---- S = Q K^T : warp computes 16 x 64 ----
        float s[8][4];
#pragma unroll
        for (int nt = 0; nt < 8; nt++)
#pragma unroll
            for (int i = 0; i < 4; i++) s[nt][i] = 0.f;

#pragma unroll
        for (int ksp = 0; ksp < 8; ksp++) {
            float4 A0 = *(float4*)&Qsf[(wq * 16 + 2 * ksp    ) * TILE_F + lane * 4];
            float4 A1 = *(float4*)&Qsf[(wq * 16 + 2 * ksp + 1) * TILE_F + lane * 4];
#pragma unroll
            for (int nt = 0; nt < 8; nt++) {
                float4 Bv = *(float4*)&Ksf[(nt * 8 + ksp) * TILE_F + lane * 4];
                mma_tf32(s[nt], U(A0.x), U(A0.y), U(A0.z), U(A0.w), U(Bv.x), U(Bv.y));
                mma_tf32(s[nt], U(A1.x), U(A1.y), U(A1.z), U(A1.w), U(Bv.z), U(Bv.w));
            }
        }

        // ---- causal mask (diagonal tile; k0 == q0) ----
        if (kt == qt) {
            int row1 = wq * 16 + g;
#pragma unroll
            for (int nt = 0; nt < 8; nt++) {
                int c0 = nt * 8 + 2 * t4;
                if (c0     > row1)     s[nt][0] = -1e30f;
                if (c0 + 1 > row1)     s[nt][1] = -1e30f;
                if (c0     > row1 + 8) s[nt][2] = -1e30f;
                if (c0 + 1 > row1 + 8) s[nt][3] = -1e30f;
            }
        }

        // ---- warp-private online softmax (rows g, g+8 of warp's 16) ----
        float mx1 = -1e30f, mx2 = -1e30f;
#pragma unroll
        for (int nt = 0; nt < 8; nt++) {
            mx1 = fmaxf(mx1, fmaxf(s[nt][0], s[nt][1]));
            mx2 = fmaxf(mx2, fmaxf(s[nt][2], s[nt][3]));
        }
        mx1 = fmaxf(mx1, __shfl_xor_sync(0xffffffffu, mx1, 1));
        mx1 = fmaxf(mx1, __shfl_xor_sync(0xffffffffu, mx1, 2));
        mx2 = fmaxf(mx2, __shfl_xor_sync(0xffffffffu, mx2, 1));
        mx2 = fmaxf(mx2, __shfl_xor_sync(0xffffffffu, mx2, 2));

        float mn1 = fmaxf(m1, mx1), mn2 = fmaxf(m2, mx2);
        float al1 = __expf(m1 - mn1), al2 = __expf(m2 - mn2);
        m1 = mn1; m2 = mn2;

        float sum1 = 0.f, sum2 = 0.f;
#pragma unroll
        for (int nt = 0; nt < 8; nt++) {
            float p0 = __expf(s[nt][0] - mn1);
            float p1 = __expf(s[nt][1] - mn1);
            float p2 = __expf(s[nt][2] - mn2);
            float p3 = __expf(s[nt][3] - mn2);
            sum1 += p0 + p1; sum2 += p2 + p3;
            s[nt][0] = f2tf(p0); s[nt][1] = f2tf(p1);
            s[nt][2] = f2tf(p2); s[nt][3] = f2tf(p3);
        }
        sum1 += __shfl_xor_sync(0xffffffffu, sum1, 1);
        sum1 += __shfl_xor_sync(0xffffffffu, sum1, 2);
        sum2 += __shfl_xor_sync(0xffffffffu, sum2, 1);
        sum2 += __shfl_xor_sync(0xffffffffu, sum2, 2);
        l1 = l1 * al1 + sum1;
        l2 = l2 * al2 + sum2;

        // ---- rescale O ----
#pragma unroll
        for (int nt = 0; nt < 16; nt++) {
            o[nt][0] *= al1; o[nt][1] *= al1;
            o[nt][2] *= al2; o[nt][3] *= al2;
        }

        // ---- O += P V : P C-frags -> A-frags via shfl, V from smem ----
#pragma unroll
        for (int ksp = 0; ksp < 4; ksp++) {
            unsigned a[2][4];
#pragma unroll
            for (int h = 0; h < 2; h++) {
                int ks = 2 * ksp + h;
                float p0 = s[ks][0], p1 = s[ks][1], p2 = s[ks][2], p3 = s[ks][3];
                int srcA = (lane & ~3) | (t4 >> 1);
                int srcB = srcA + 2;
                float u0 = __shfl_sync(0xffffffffu, p0, srcA);
                float v0 = __shfl_sync(0xffffffffu, p1, srcA);
                float u1 = __shfl_sync(0xffffffffu, p2, srcA);
                float v1 = __shfl_sync(0xffffffffu, p3, srcA);
                float u2 = __shfl_sync(0xffffffffu, p0, srcB);
                float v2 = __shfl_sync(0xffffffffu, p1, srcB);
                float u3 = __shfl_sync(0xffffffffu, p2, srcB);
                float v3 = __shfl_sync(0xffffffffu, p3, srcB);
                bool odd = (t4 & 1);
                a[h][0] = U(odd ? v0 : u0);
                a[h][1] = U(odd ? v1 : u1);
                a[h][2] = U(odd ? v2 : u2);
                a[h][3] = U(odd ? v3 : u3);
            }
#pragma unroll
            for (int nt = 0; nt < 16; nt++) {
                float4 Bv = *(float4*)&Vsf[(nt * 4 + ksp) * TILE_F + lane * 4];
                mma_tf32(o[nt], a[0][0], a[0][1], a[0][2], a[0][3], U(Bv.x), U(Bv.y));
                mma_tf32(o[nt], a[1][0], a[1][1], a[1][2], a[1][3], U(Bv.z), U(Bv.w));
            }
        }
    }

    // ---- epilogue ----
    {
        float inv1 = 1.f / l1, inv2 = 1.f / l2;
        size_t base1 = ((size_t)b * TT + q0 + wq * 16 + g) * HH;
        size_t base2 = base1 + 8 * HH;
#pragma unroll
        for (int nt = 0; nt < 16; nt++) {
            int col = nt * 8 + 2 * t4;
            *(float2*)&out[base1 + col] = make_float2(o[nt][0] * inv1, o[nt][1] * inv1);
            *(float2*)&out[base2 + col] = make_float2(o[nt][2] * inv2, o[nt][3] * inv2);
        }
    }
}

// ---------------------------------------------------------------------------
extern "C" void kernel_launch(void* const* d_in, const int* in_sizes, int n_in,
                              void* d_out, int out_size)
{
    const float* x  = (const float*)d_in[0];
    const float* Wq = (const float*)d_in[1];
    const float* Wk = (const float*)d_in[2];
    const float* Wv = (const float*)d_in[3];
    float* out = (float*)d_out;

    qkv_kernel<<<dim3(MM / 128, 3), 256>>>(x, Wq, Wk, Wv);

    cudaFuncSetAttribute(attn_kernel,
                         cudaFuncAttributeMaxDynamicSharedMemorySize, ATTN_SMEM);
    attn_kernel<<<dim3(32, BB), 128, ATTN_SMEM>>>(out);
}